// round 7
// baseline (speedup 1.0000x reference)
#include <cuda_runtime.h>
#include <cstdint>

// Scratch (static device globals — no allocation).
__device__ float g_Tpart[8][32][8192];    // 8 MB: pose-chunk partials of T[b][g]
__device__ float g_pp[128][2048];         // 1 MB: stage2 partial pooled [slot][b*64+c]

// ---- packed f32x2 helpers ----
__device__ __forceinline__ unsigned long long pack2(float x, float y) {
    unsigned long long r;
    asm("mov.b64 %0, {%1,%2};" : "=l"(r) : "f"(x), "f"(y));
    return r;
}
__device__ __forceinline__ void fma2(unsigned long long& d, unsigned long long a, unsigned long long b) {
    asm("fma.rn.f32x2 %0, %1, %2, %0;" : "+l"(d) : "l"(a), "l"(b));
}
__device__ __forceinline__ float2 unpk(unsigned long long v) {
    float2 r;
    asm("mov.b64 {%0,%1}, %2;" : "=f"(r.x), "=f"(r.y) : "l"(v));
    return r;
}

// ============================================================================
// Stage 1 (warp-autonomous): T[b, j*64 + r*8 + x] += (CP[b,i] @ Wc[i])[r][x]
// over poses, i = pose*128 + j.
// Warp gw (4096 total): bp = gw&15 (b pair), jg = (gw>>4)&31 (4 j's),
// sc = gw>>9 (8 poses). Lane l owns row r=l&7 of matrix q=l>>3 for both b's
// (full row via float4 pair 2l, 2l+1 of the contiguous 1KB chunk).
// W staged per-warp in bank-skewed smem (stride 72), double-buffered,
// __syncwarp only. Depth-1 register prefetch.
// ============================================================================
__global__ void __launch_bounds__(64) k_stage1(const float* __restrict__ cp,
                                               const float* __restrict__ wc) {
    const int tid = threadIdx.x;
    const int wip = tid >> 5;
    const int l   = tid & 31;
    const int gw  = blockIdx.x * 2 + wip;
    const int bp  = gw & 15;
    const int jg  = (gw >> 4) & 31;
    const int sc  = gw >> 9;             // 0..7
    const int b0  = bp * 2, b1 = b0 + 1;
    const int j0  = jg * 4;
    const int p0  = sc * 8;
    const int q   = l >> 3;

    __shared__ float sW[2][2][288];   // [warp][buf][4*72]

    // STS offsets for W float4s f=l and f=l+32:  q'*72 + m*8 + h*4
    const int f0 = l, f1 = l + 32;
    const int so0 = (f0 >> 4) * 72 + ((f0 & 15) >> 1) * 8 + (f0 & 1) * 4;
    const int so1 = (f1 >> 4) * 72 + ((f1 & 15) >> 1) * 8 + (f1 & 1) * 4;

    const float4* a0p = reinterpret_cast<const float4*>(cp)
                        + ((size_t)b0 * 8192 + (size_t)p0 * 128 + j0) * 16;
    const float4* a1p = reinterpret_cast<const float4*>(cp)
                        + ((size_t)b1 * 8192 + (size_t)p0 * 128 + j0) * 16;
    const float4* wp  = reinterpret_cast<const float4*>(wc)
                        + ((size_t)p0 * 128 + j0) * 16;

    float4 A0[2][2], A1[2][2], Wr[2][2];
    A0[0][0] = a0p[2 * l]; A0[0][1] = a0p[2 * l + 1];
    A1[0][0] = a1p[2 * l]; A1[0][1] = a1p[2 * l + 1];
    Wr[0][0] = wp[f0];     Wr[0][1] = wp[f1];

    unsigned long long acc0[4] = {0ull, 0ull, 0ull, 0ull};
    unsigned long long acc1[4] = {0ull, 0ull, 0ull, 0ull};

#pragma unroll 2
    for (int it = 0; it < 8; ++it) {
        const int cur = it & 1, nxt = cur ^ 1;
        float* sw = sW[wip][cur];
        *reinterpret_cast<float4*>(sw + so0) = Wr[cur][0];
        *reinterpret_cast<float4*>(sw + so1) = Wr[cur][1];
        __syncwarp();

        if (it < 7) {                  // prefetch next pose (+2048 float4)
            a0p += 2048; a1p += 2048; wp += 2048;
            A0[nxt][0] = a0p[2 * l]; A0[nxt][1] = a0p[2 * l + 1];
            A1[nxt][0] = a1p[2 * l]; A1[nxt][1] = a1p[2 * l + 1];
            Wr[nxt][0] = wp[f0];     Wr[nxt][1] = wp[f1];
        }

        const float am0[8] = {A0[cur][0].x, A0[cur][0].y, A0[cur][0].z, A0[cur][0].w,
                              A0[cur][1].x, A0[cur][1].y, A0[cur][1].z, A0[cur][1].w};
        const float am1[8] = {A1[cur][0].x, A1[cur][0].y, A1[cur][0].z, A1[cur][0].w,
                              A1[cur][1].x, A1[cur][1].y, A1[cur][1].z, A1[cur][1].w};
        const float* wq = sw + q * 72;
#pragma unroll
        for (int m = 0; m < 8; ++m) {
            const ulonglong2 wlo = *reinterpret_cast<const ulonglong2*>(wq + m * 8);
            const ulonglong2 whi = *reinterpret_cast<const ulonglong2*>(wq + m * 8 + 4);
            const unsigned long long pa0 = pack2(am0[m], am0[m]);
            const unsigned long long pa1 = pack2(am1[m], am1[m]);
            fma2(acc0[0], pa0, wlo.x); fma2(acc0[1], pa0, wlo.y);
            fma2(acc0[2], pa0, whi.x); fma2(acc0[3], pa0, whi.y);
            fma2(acc1[0], pa1, wlo.x); fma2(acc1[1], pa1, wlo.y);
            fma2(acc1[2], pa1, whi.x); fma2(acc1[3], pa1, whi.y);
        }
        __syncwarp();
    }

    // Lane writes T rows: floats j0*64 + l*8 .. +8  (float4 idx jg*64 + 2l).
    {
        float2 v0 = unpk(acc0[0]), v1 = unpk(acc0[1]);
        float2 v2 = unpk(acc0[2]), v3 = unpk(acc0[3]);
        float4* d0 = reinterpret_cast<float4*>(&g_Tpart[sc][b0][j0 * 64]);
        d0[2 * l]     = make_float4(v0.x, v0.y, v1.x, v1.y);
        d0[2 * l + 1] = make_float4(v2.x, v2.y, v3.x, v3.y);
        v0 = unpk(acc1[0]); v1 = unpk(acc1[1]);
        v2 = unpk(acc1[2]); v3 = unpk(acc1[3]);
        float4* d1 = reinterpret_cast<float4*>(&g_Tpart[sc][b1][j0 * 64]);
        d1[2 * l]     = make_float4(v0.x, v0.y, v1.x, v1.y);
        d1[2 * l + 1] = make_float4(v2.x, v2.y, v3.x, v3.y);
    }
}

// ============================================================================
// Stage 2: fold 8 pose-chunk partials of T; E folded over hid%64 at load:
//   pp[b,c] += T[b,g] * (E[g][c] + E[g][c+64] + E[g][c+128] + E[g][c+192])
// 128 blocks x 256 threads; block owns 64 g; thread = (c 64, gq 4) x 16 g.
// gq-partials folded in-block through smem -> ONE g_pp slot per block.
// ============================================================================
__global__ void __launch_bounds__(256) k_stage2(const float* __restrict__ E) {
    const int g0  = blockIdx.x * 64;
    const int tid = threadIdx.x;
    __shared__ float sT[64][34];
    __shared__ float sF[4][2048];

#pragma unroll
    for (int k = 0; k < 8; ++k) {
        const int e = k * 256 + tid;
        const int b = e >> 6, gg = e & 63;
        float s = 0.f;
#pragma unroll
        for (int pc = 0; pc < 8; ++pc) s += g_Tpart[pc][b][g0 + gg];
        sT[gg][b] = s;
    }
    __syncthreads();

    const int c  = tid & 63;
    const int gq = tid >> 6;
    unsigned long long acc[16];
#pragma unroll
    for (int i = 0; i < 16; ++i) acc[i] = 0ull;

    const float* Eb = E + (size_t)g0 * 256 + c;
#pragma unroll 2
    for (int t = 0; t < 16; ++t) {
        const int gg = gq * 16 + t;
        const float* er = Eb + (size_t)gg * 256;
        const float ev = er[0] + er[64] + er[128] + er[192];
        const unsigned long long ep = pack2(ev, ev);
        const unsigned long long* t2 =
            reinterpret_cast<const unsigned long long*>(&sT[gg][0]);
#pragma unroll
        for (int bb = 0; bb < 16; ++bb) fma2(acc[bb], t2[bb], ep);
    }

    // Spill per-gq partials (lane-consecutive c -> conflict-free).
#pragma unroll
    for (int bb = 0; bb < 16; ++bb) {
        float2 v = unpk(acc[bb]);
        sF[gq][(2 * bb + 0) * 64 + c] = v.x;
        sF[gq][(2 * bb + 1) * 64 + c] = v.y;
    }
    __syncthreads();

    // Fold gq and write ONE slot for this block.
    float* dst = g_pp[blockIdx.x];
#pragma unroll
    for (int k = 0; k < 8; ++k) {
        const int e = k * 256 + tid;
        dst[e] = sF[0][e] + sF[1][e] + sF[2][e] + sF[3][e];
    }
}

// ============================================================================
// Final: pooled[b,c] = (sum of 128 slots)/64 + rel[c];
//        out[b,o] = pooled(8x8) @ w_next[o].   32 blocks x 256 threads.
// ============================================================================
__global__ void __launch_bounds__(256) k_final(const float* __restrict__ wn,
                                               const float* __restrict__ rel,
                                               float* __restrict__ out) {
    const int b   = blockIdx.x;
    const int tid = threadIdx.x;
    const int c   = tid & 63, qd = tid >> 6;
    __shared__ float sN[64];
    __shared__ float sP[4][64];
    __shared__ float sWn[4096];

    float s = 0.f;
#pragma unroll 8
    for (int k = 0; k < 32; ++k) s += g_pp[qd * 32 + k][b * 64 + c];
    sP[qd][c] = s;

    {
        float4* s4 = reinterpret_cast<float4*>(sWn);
        const float4* w4 = reinterpret_cast<const float4*>(wn);
#pragma unroll
        for (int k = 0; k < 4; ++k) s4[k * 256 + tid] = w4[k * 256 + tid];
    }
    __syncthreads();
    if (tid < 64) {
        sN[tid] = (sP[0][tid] + sP[1][tid] + sP[2][tid] + sP[3][tid]) * (1.f / 64.f)
                  + rel[tid];
    }
    __syncthreads();

    const int r = c >> 3, col = c & 7;
    float a[8];
#pragma unroll
    for (int m = 0; m < 8; ++m) a[m] = sN[r * 8 + m];
    float* ob = out + (size_t)b * 4096;
#pragma unroll 4
    for (int o = qd * 16; o < qd * 16 + 16; ++o) {
        float accv = 0.f;
#pragma unroll
        for (int m = 0; m < 8; ++m) accv += a[m] * sWn[o * 64 + m * 8 + col];
        ob[o * 64 + c] = accv;
    }
}

extern "C" void kernel_launch(void* const* d_in, const int* in_sizes, int n_in,
                              void* d_out, int out_size) {
    const float* cp  = (const float*)d_in[0];  // current_pose (32,8192,64)
    const float* wc  = (const float*)d_in[1];  // w_current    (8192,8,8)
    const float* wn  = (const float*)d_in[2];  // w_next       (64,8,8)
    const float* E   = (const float*)d_in[3];  // E_proj       (32,256,256)
    const float* rel = (const float*)d_in[4];  // rel_embedd   (64)
    float* out = (float*)d_out;                // (32,64,64) fp32

    k_stage1<<<2048, 64>>>(cp, wc);
    k_stage2<<<128, 256>>>(E);
    k_final<<<32, 256>>>(wn, rel, out);
}

// round 8
// speedup vs baseline: 1.3089x; 1.3089x over previous
#include <cuda_runtime.h>
#include <cstdint>

// Scratch (static device globals — no allocation).
__device__ float g_Tpart[4][32][8192];    // 4 MB: pose-chunk partials of T[b][g]
__device__ float g_pp[128][2048];         // 1 MB: stage2 partial pooled [slot][b*64+c]

// ---- packed f32x2 helpers ----
__device__ __forceinline__ unsigned long long pack2(float x, float y) {
    unsigned long long r;
    asm("mov.b64 %0, {%1,%2};" : "=l"(r) : "f"(x), "f"(y));
    return r;
}
__device__ __forceinline__ void fma2(unsigned long long& d, unsigned long long a, unsigned long long b) {
    asm("fma.rn.f32x2 %0, %1, %2, %0;" : "+l"(d) : "l"(a), "l"(b));
}
__device__ __forceinline__ float2 unpk(unsigned long long v) {
    float2 r;
    asm("mov.b64 {%0,%1}, %2;" : "=f"(r.x), "=f"(r.y) : "l"(v));
    return r;
}

// ============================================================================
// Stage 1 (warp-autonomous, 4 batches/warp): T[b, j*64 + r*8 + x] +=
//   (CP[b,i] @ Wc[i])[r][x] over poses, i = pose*128 + j.
// Warp gw (1024): bq = gw&7 (4 b's), jg = (gw>>3)&31 (4 j's), sc = gw>>8
// (16 poses). Lane l owns row r=l&7 of matrix q=l>>3 for all 4 b's (full
// row via float4 pair 2l, 2l+1 of the contiguous 1KB chunk). W staged
// per-warp in bank-skewed smem (stride 72), double-buffered, __syncwarp
// only. The 16 LDS + 2 STS per pose are amortized over 4 KB of A data
// (LSU instrs/KB: 12 -> 7; stage1 was LSU-issue-bound at 2 b's).
// ============================================================================
__global__ void __launch_bounds__(64) k_stage1(const float* __restrict__ cp,
                                               const float* __restrict__ wc) {
    const int tid = threadIdx.x;
    const int wip = tid >> 5;
    const int l   = tid & 31;
    const int gw  = blockIdx.x * 2 + wip;   // 0..1023
    const int bq  = gw & 7;
    const int jg  = (gw >> 3) & 31;
    const int sc  = gw >> 8;                // 0..3
    const int b0  = bq * 4;
    const int j0  = jg * 4;
    const int p0  = sc * 16;
    const int q   = l >> 3;

    __shared__ float sW[2][2][288];   // [warp][buf][4*72]

    // STS offsets for W float4s f=l and f=l+32:  q'*72 + m*8 + h*4
    const int f0 = l, f1 = l + 32;
    const int so0 = (f0 >> 4) * 72 + ((f0 & 15) >> 1) * 8 + (f0 & 1) * 4;
    const int so1 = (f1 >> 4) * 72 + ((f1 & 15) >> 1) * 8 + (f1 & 1) * 4;

    const float4* ap[4];
#pragma unroll
    for (int bb = 0; bb < 4; ++bb)
        ap[bb] = reinterpret_cast<const float4*>(cp)
                 + ((size_t)(b0 + bb) * 8192 + (size_t)p0 * 128 + j0) * 16;
    const float4* wp = reinterpret_cast<const float4*>(wc)
                       + ((size_t)p0 * 128 + j0) * 16;

    float4 A[2][4][2];   // [buf][b][pair]
    float4 Wr[2][2];
#pragma unroll
    for (int bb = 0; bb < 4; ++bb) {
        A[0][bb][0] = ap[bb][2 * l];
        A[0][bb][1] = ap[bb][2 * l + 1];
    }
    Wr[0][0] = wp[f0]; Wr[0][1] = wp[f1];

    unsigned long long acc[4][4];
#pragma unroll
    for (int bb = 0; bb < 4; ++bb)
#pragma unroll
        for (int c = 0; c < 4; ++c) acc[bb][c] = 0ull;

#pragma unroll 2
    for (int it = 0; it < 16; ++it) {
        const int cur = it & 1, nxt = cur ^ 1;
        float* sw = sW[wip][cur];
        *reinterpret_cast<float4*>(sw + so0) = Wr[cur][0];
        *reinterpret_cast<float4*>(sw + so1) = Wr[cur][1];
        __syncwarp();

        if (it < 15) {                 // prefetch next pose (+2048 float4)
#pragma unroll
            for (int bb = 0; bb < 4; ++bb) {
                ap[bb] += 2048;
                A[nxt][bb][0] = ap[bb][2 * l];
                A[nxt][bb][1] = ap[bb][2 * l + 1];
            }
            wp += 2048;
            Wr[nxt][0] = wp[f0]; Wr[nxt][1] = wp[f1];
        }

        float am[4][8];
#pragma unroll
        for (int bb = 0; bb < 4; ++bb) {
            am[bb][0] = A[cur][bb][0].x; am[bb][1] = A[cur][bb][0].y;
            am[bb][2] = A[cur][bb][0].z; am[bb][3] = A[cur][bb][0].w;
            am[bb][4] = A[cur][bb][1].x; am[bb][5] = A[cur][bb][1].y;
            am[bb][6] = A[cur][bb][1].z; am[bb][7] = A[cur][bb][1].w;
        }
        const float* wq = sw + q * 72;
#pragma unroll
        for (int m = 0; m < 8; ++m) {
            const ulonglong2 wlo = *reinterpret_cast<const ulonglong2*>(wq + m * 8);
            const ulonglong2 whi = *reinterpret_cast<const ulonglong2*>(wq + m * 8 + 4);
#pragma unroll
            for (int bb = 0; bb < 4; ++bb) {
                const unsigned long long pa = pack2(am[bb][m], am[bb][m]);
                fma2(acc[bb][0], pa, wlo.x); fma2(acc[bb][1], pa, wlo.y);
                fma2(acc[bb][2], pa, whi.x); fma2(acc[bb][3], pa, whi.y);
            }
        }
        __syncwarp();
    }

    // Lane writes T rows: floats j0*64 + l*8 .. +8  (float4 idx jg*64 + 2l).
#pragma unroll
    for (int bb = 0; bb < 4; ++bb) {
        float2 v0 = unpk(acc[bb][0]), v1 = unpk(acc[bb][1]);
        float2 v2 = unpk(acc[bb][2]), v3 = unpk(acc[bb][3]);
        float4* d = reinterpret_cast<float4*>(&g_Tpart[sc][b0 + bb][j0 * 64]);
        d[2 * l]     = make_float4(v0.x, v0.y, v1.x, v1.y);
        d[2 * l + 1] = make_float4(v2.x, v2.y, v3.x, v3.y);
    }
}

// ============================================================================
// Stage 2: fold 4 pose-chunk partials of T; E folded over hid%64 at load:
//   pp[b,c] += T[b,g] * (E[g][c] + E[g][c+64] + E[g][c+128] + E[g][c+192])
// 128 blocks x 256 threads; block owns 64 g; thread = (c 64, gq 4) x 16 g.
// gq-partials folded in-block through smem -> ONE g_pp slot per block.
// ============================================================================
__global__ void __launch_bounds__(256) k_stage2(const float* __restrict__ E) {
    const int g0  = blockIdx.x * 64;
    const int tid = threadIdx.x;
    __shared__ float sT[64][34];
    __shared__ float sF[4][2048];

#pragma unroll
    for (int k = 0; k < 8; ++k) {
        const int e = k * 256 + tid;
        const int b = e >> 6, gg = e & 63;
        sT[gg][b] = g_Tpart[0][b][g0 + gg] + g_Tpart[1][b][g0 + gg]
                  + g_Tpart[2][b][g0 + gg] + g_Tpart[3][b][g0 + gg];
    }
    __syncthreads();

    const int c  = tid & 63;
    const int gq = tid >> 6;
    unsigned long long acc[16];
#pragma unroll
    for (int i = 0; i < 16; ++i) acc[i] = 0ull;

    const float* Eb = E + (size_t)g0 * 256 + c;
#pragma unroll 2
    for (int t = 0; t < 16; ++t) {
        const int gg = gq * 16 + t;
        const float* er = Eb + (size_t)gg * 256;
        const float ev = er[0] + er[64] + er[128] + er[192];
        const unsigned long long ep = pack2(ev, ev);
        const unsigned long long* t2 =
            reinterpret_cast<const unsigned long long*>(&sT[gg][0]);
#pragma unroll
        for (int bb = 0; bb < 16; ++bb) fma2(acc[bb], t2[bb], ep);
    }

    // Spill per-gq partials (lane-consecutive c -> conflict-free).
#pragma unroll
    for (int bb = 0; bb < 16; ++bb) {
        float2 v = unpk(acc[bb]);
        sF[gq][(2 * bb + 0) * 64 + c] = v.x;
        sF[gq][(2 * bb + 1) * 64 + c] = v.y;
    }
    __syncthreads();

    // Fold gq and write ONE slot for this block.
    float* dst = g_pp[blockIdx.x];
#pragma unroll
    for (int k = 0; k < 8; ++k) {
        const int e = k * 256 + tid;
        dst[e] = sF[0][e] + sF[1][e] + sF[2][e] + sF[3][e];
    }
}

// ============================================================================
// Final: pooled[b,c] = (sum of 128 slots)/64 + rel[c];
//        out[b,o] = pooled(8x8) @ w_next[o].   32 blocks x 256 threads.
// ============================================================================
__global__ void __launch_bounds__(256) k_final(const float* __restrict__ wn,
                                               const float* __restrict__ rel,
                                               float* __restrict__ out) {
    const int b   = blockIdx.x;
    const int tid = threadIdx.x;
    const int c   = tid & 63, qd = tid >> 6;
    __shared__ float sN[64];
    __shared__ float sP[4][64];
    __shared__ float sWn[4096];

    float s = 0.f;
#pragma unroll 8
    for (int k = 0; k < 32; ++k) s += g_pp[qd * 32 + k][b * 64 + c];
    sP[qd][c] = s;

    {
        float4* s4 = reinterpret_cast<float4*>(sWn);
        const float4* w4 = reinterpret_cast<const float4*>(wn);
#pragma unroll
        for (int k = 0; k < 4; ++k) s4[k * 256 + tid] = w4[k * 256 + tid];
    }
    __syncthreads();
    if (tid < 64) {
        sN[tid] = (sP[0][tid] + sP[1][tid] + sP[2][tid] + sP[3][tid]) * (1.f / 64.f)
                  + rel[tid];
    }
    __syncthreads();

    const int r = c >> 3, col = c & 7;
    float a[8];
#pragma unroll
    for (int m = 0; m < 8; ++m) a[m] = sN[r * 8 + m];
    float* ob = out + (size_t)b * 4096;
#pragma unroll 4
    for (int o = qd * 16; o < qd * 16 + 16; ++o) {
        float accv = 0.f;
#pragma unroll
        for (int m = 0; m < 8; ++m) accv += a[m] * sWn[o * 64 + m * 8 + col];
        ob[o * 64 + c] = accv;
    }
}

extern "C" void kernel_launch(void* const* d_in, const int* in_sizes, int n_in,
                              void* d_out, int out_size) {
    const float* cp  = (const float*)d_in[0];  // current_pose (32,8192,64)
    const float* wc  = (const float*)d_in[1];  // w_current    (8192,8,8)
    const float* wn  = (const float*)d_in[2];  // w_next       (64,8,8)
    const float* E   = (const float*)d_in[3];  // E_proj       (32,256,256)
    const float* rel = (const float*)d_in[4];  // rel_embedd   (64)
    float* out = (float*)d_out;                // (32,64,64) fp32

    k_stage1<<<512, 64>>>(cp, wc);
    k_stage2<<<128, 256>>>(E);
    k_final<<<32, 256>>>(wn, rel, out);
}